// round 1
// baseline (speedup 1.0000x reference)
#include <cuda_runtime.h>
#include <cuda_bf16.h>
#include <cstddef>

// Problem constants (shapes fixed by the dataset)
#define NNODES 50000
#define NFEAT  128
#define KTOP   32

// Device-global scratch (no allocations allowed)
__device__ float g_agg[NNODES * NFEAT];    // aggregated neighbor features
__device__ float g_deg[NNODES];            // in-degree (float, exact for counts < 2^24)
__device__ float g_vclean[NNODES * KTOP];  // topk values with duplicate-index losers zeroed

// ---------------------------------------------------------------------------
// K1: in-degree histogram over dst
// ---------------------------------------------------------------------------
__global__ void deg_kernel(const int* __restrict__ dst, float* __restrict__ deg, int e) {
    int i = blockIdx.x * blockDim.x + threadIdx.x;
    if (i < e) atomicAdd(&deg[dst[i]], 1.0f);
}

// ---------------------------------------------------------------------------
// K2: dedup topk values. JAX scatter-set applies updates in order -> last
// (highest k) wins for duplicate indices within a row. One warp per node row;
// lane k keeps its value only if it is the highest lane among equal indices.
// ---------------------------------------------------------------------------
__global__ void clean_kernel(const int* __restrict__ tindices,
                             const float* __restrict__ tvalues,
                             float* __restrict__ vclean, int n) {
    int gtid = blockIdx.x * blockDim.x + threadIdx.x;
    int row  = gtid >> 5;
    int lane = gtid & 31;
    if (row >= n) return;
    int   idx = tindices[row * KTOP + lane];
    float v   = tvalues[row * KTOP + lane];
    unsigned mask = __match_any_sync(0xFFFFFFFFu, idx);
    int leader = 31 - __clz(mask);   // highest lane with this index wins
    vclean[row * KTOP + lane] = (lane == leader) ? v : 0.0f;
}

// ---------------------------------------------------------------------------
// K3: sparse scatter-add SpMM. One warp per edge; lane k does one atomicAdd
// into agg[dst]. agg (25.6MB) is L2-resident.
// ---------------------------------------------------------------------------
__global__ void scatter_kernel(const int* __restrict__ src,
                               const int* __restrict__ dst,
                               const int* __restrict__ tindices,
                               const float* __restrict__ vclean,
                               const float* __restrict__ deg,
                               float* __restrict__ agg, int e) {
    int gtid = blockIdx.x * blockDim.x + threadIdx.x;
    int edge = gtid >> 5;
    int lane = gtid & 31;
    if (edge >= e) return;
    int s = src[edge];
    int d = dst[edge];
    float w = 1.0f / fmaxf(deg[d], 1.0f);
    int   idx = tindices[s * KTOP + lane];
    float v   = vclean[s * KTOP + lane];
    if (v != 0.0f) atomicAdd(&agg[d * NFEAT + idx], w * v);
}

// ---------------------------------------------------------------------------
// K4: fused GEMM epilogue:
//   out = feat @ W_self + agg @ W_neigh + b_self
// Treated as [feat | agg] (Mx256) @ [W_self ; W_neigh] (256x128).
// 128x128 block tile, 8x8 per-thread register tile, 16-deep k chunks.
// ---------------------------------------------------------------------------
__global__ __launch_bounds__(256, 2)
void gemm_kernel(const float* __restrict__ feat,
                 const float* __restrict__ agg,
                 const float* __restrict__ Wself,
                 const float* __restrict__ Wneigh,
                 const float* __restrict__ bself,
                 float* __restrict__ out, int n) {
    __shared__ float a_sh[16][132];   // [k][row], padded
    __shared__ float w_sh[16][128];   // [k][col]

    const int row0 = blockIdx.x * 128;
    const int tid  = threadIdx.x;
    const int tx   = tid & 15;        // col group (8 cols each)
    const int ty   = tid >> 4;        // row group (8 rows each)

    float acc[8][8];
#pragma unroll
    for (int i = 0; i < 8; i++)
#pragma unroll
        for (int j = 0; j < 8; j++) acc[i][j] = 0.0f;

#pragma unroll 1
    for (int pass = 0; pass < 2; pass++) {
        const float* A = pass ? agg : feat;
        const float* W = pass ? Wneigh : Wself;
#pragma unroll 1
        for (int k0 = 0; k0 < 128; k0 += 16) {
            // --- stage A tile (transposed into [k][row]) ---
            {
                int r  = tid & 127;
                int kb = (tid >> 7) << 3;   // 0 or 8
                float4 v0 = make_float4(0.f, 0.f, 0.f, 0.f);
                float4 v1 = v0;
                if (row0 + r < n) {
                    const float* ap = A + (size_t)(row0 + r) * NFEAT + k0 + kb;
                    v0 = *(const float4*)ap;
                    v1 = *(const float4*)(ap + 4);
                }
                a_sh[kb + 0][r] = v0.x; a_sh[kb + 1][r] = v0.y;
                a_sh[kb + 2][r] = v0.z; a_sh[kb + 3][r] = v0.w;
                a_sh[kb + 4][r] = v1.x; a_sh[kb + 5][r] = v1.y;
                a_sh[kb + 6][r] = v1.z; a_sh[kb + 7][r] = v1.w;
            }
            // --- stage W tile ---
            {
                int kk = tid >> 5;            // 0..7
                int c4 = (tid & 31) << 2;     // 0,4,...,124
                *(float4*)&w_sh[kk][c4]     = *(const float4*)&W[(k0 + kk) * NFEAT + c4];
                *(float4*)&w_sh[kk + 8][c4] = *(const float4*)&W[(k0 + kk + 8) * NFEAT + c4];
            }
            __syncthreads();

#pragma unroll
            for (int kq = 0; kq < 16; kq++) {
                float a[8], b[8];
                *(float4*)&a[0] = *(const float4*)&a_sh[kq][ty * 8];
                *(float4*)&a[4] = *(const float4*)&a_sh[kq][ty * 8 + 4];
                *(float4*)&b[0] = *(const float4*)&w_sh[kq][tx * 8];
                *(float4*)&b[4] = *(const float4*)&w_sh[kq][tx * 8 + 4];
#pragma unroll
                for (int i = 0; i < 8; i++)
#pragma unroll
                    for (int j = 0; j < 8; j++)
                        acc[i][j] = fmaf(a[i], b[j], acc[i][j]);
            }
            __syncthreads();
        }
    }

    // epilogue: add bias, store
#pragma unroll
    for (int i = 0; i < 8; i++) {
        int rr = row0 + ty * 8 + i;
        if (rr < n) {
#pragma unroll
            for (int j = 0; j < 8; j += 4) {
                float4 o;
                o.x = acc[i][j + 0] + bself[tx * 8 + j + 0];
                o.y = acc[i][j + 1] + bself[tx * 8 + j + 1];
                o.z = acc[i][j + 2] + bself[tx * 8 + j + 2];
                o.w = acc[i][j + 3] + bself[tx * 8 + j + 3];
                *(float4*)&out[(size_t)rr * NFEAT + tx * 8 + j] = o;
            }
        }
    }
}

// ---------------------------------------------------------------------------
// Launch: all on the default stream (graph-capturable), no allocations.
// Input order (setup_inputs dict order):
//   0 feat [N,128] f32 | 1 topk_values [N,32] f32 | 2 topk_indices [N,32] i32
//   3 src [E] i32 | 4 dst [E] i32 | 5 W_self [128,128] f32 | 6 b_self [128] f32
//   7 W_neigh [128,128] f32
// ---------------------------------------------------------------------------
extern "C" void kernel_launch(void* const* d_in, const int* in_sizes, int n_in,
                              void* d_out, int out_size) {
    const float* feat     = (const float*)d_in[0];
    const float* tvalues  = (const float*)d_in[1];
    const int*   tindices = (const int*)d_in[2];
    const int*   src      = (const int*)d_in[3];
    const int*   dst      = (const int*)d_in[4];
    const float* Wself    = (const float*)d_in[5];
    const float* bself    = (const float*)d_in[6];
    const float* Wneigh   = (const float*)d_in[7];
    float*       out      = (float*)d_out;

    const int n = in_sizes[0] / NFEAT;   // 50000
    const int e = in_sizes[3];           // 800000

    float *aggp, *degp, *vcleanp;
    cudaGetSymbolAddress((void**)&aggp, g_agg);
    cudaGetSymbolAddress((void**)&degp, g_deg);
    cudaGetSymbolAddress((void**)&vcleanp, g_vclean);

    cudaMemsetAsync(aggp, 0, (size_t)n * NFEAT * sizeof(float));
    cudaMemsetAsync(degp, 0, (size_t)n * sizeof(float));

    deg_kernel<<<(e + 255) / 256, 256>>>(dst, degp, e);
    clean_kernel<<<(n * KTOP + 255) / 256, 256>>>(tindices, tvalues, vcleanp, n);
    {
        long long total = (long long)e * 32;
        int blocks = (int)((total + 255) / 256);
        scatter_kernel<<<blocks, 256>>>(src, dst, tindices, vcleanp, degp, aggp, e);
    }
    gemm_kernel<<<(n + 127) / 128, 256>>>(feat, aggp, Wself, Wneigh, bself, out, n);
}

// round 2
// speedup vs baseline: 2.1942x; 2.1942x over previous
#include <cuda_runtime.h>
#include <cuda_bf16.h>
#include <cstddef>

#define NNODES 50000
#define NFEAT  128
#define KTOP   32
#define EDGES  800000
#define FULLM  0xFFFFFFFFu

// ---------------- device scratch (no allocation allowed) ----------------
__device__ int   g_cnt[NNODES];         // in-degree counts
__device__ int   g_rowstart[NNODES];    // CSR row starts (by dst)
__device__ int   g_cursor[NNODES];      // fill cursors
__device__ int   g_bsum[256];           // block sums for scan
__device__ int   g_boff[256];           // block offsets
__device__ int   g_col[EDGES];          // CSR column (src) array
__device__ float g_Y[NNODES * NFEAT];   // Y = Xsp @ W_neigh
__device__ float g_hagg[NNODES * NFEAT];// normalized neighbor aggregate

// ---------------------------------------------------------------------------
// K1: in-degree histogram (int)
// ---------------------------------------------------------------------------
__global__ void count_kernel(const int* __restrict__ dst, int e) {
    int i = blockIdx.x * blockDim.x + threadIdx.x;
    if (i < e) atomicAdd(&g_cnt[dst[i]], 1);
}

// ---------------------------------------------------------------------------
// K2a: per-256-block sums of g_cnt
// ---------------------------------------------------------------------------
__global__ void blocksum_kernel() {
    int i = blockIdx.x * 256 + threadIdx.x;
    int v = (i < NNODES) ? g_cnt[i] : 0;
#pragma unroll
    for (int o = 16; o > 0; o >>= 1) v += __shfl_down_sync(FULLM, v, o);
    __shared__ int ws[8];
    if ((threadIdx.x & 31) == 0) ws[threadIdx.x >> 5] = v;
    __syncthreads();
    if (threadIdx.x == 0) {
        int t = 0;
#pragma unroll
        for (int k = 0; k < 8; k++) t += ws[k];
        g_bsum[blockIdx.x] = t;
    }
}

// ---------------------------------------------------------------------------
// K2b: exclusive scan of block sums (single block, 256 threads)
// ---------------------------------------------------------------------------
__global__ void scanpartials_kernel(int nblk) {
    __shared__ int sh[256];
    int t = threadIdx.x;
    int v = (t < nblk) ? g_bsum[t] : 0;
    sh[t] = v;
    __syncthreads();
#pragma unroll
    for (int o = 1; o < 256; o <<= 1) {
        int x = (t >= o) ? sh[t - o] : 0;
        __syncthreads();
        sh[t] += x;
        __syncthreads();
    }
    g_boff[t] = sh[t] - v;   // exclusive
}

// ---------------------------------------------------------------------------
// K2c: per-block exclusive scan -> rowstart, cursor
// ---------------------------------------------------------------------------
__global__ void localscan_kernel() {
    __shared__ int sh[256];
    int t = threadIdx.x;
    int i = blockIdx.x * 256 + t;
    int v = (i < NNODES) ? g_cnt[i] : 0;
    sh[t] = v;
    __syncthreads();
#pragma unroll
    for (int o = 1; o < 256; o <<= 1) {
        int x = (t >= o) ? sh[t - o] : 0;
        __syncthreads();
        sh[t] += x;
        __syncthreads();
    }
    if (i < NNODES) {
        int excl = sh[t] - v + g_boff[blockIdx.x];
        g_rowstart[i] = excl;
        g_cursor[i]   = excl;
    }
}

// ---------------------------------------------------------------------------
// K3: fill CSR column array (src per dst-slot)
// ---------------------------------------------------------------------------
__global__ void fill_kernel(const int* __restrict__ src, const int* __restrict__ dst, int e) {
    int i = blockIdx.x * blockDim.x + threadIdx.x;
    if (i < e) {
        int d = dst[i];
        int pos = atomicAdd(&g_cursor[d], 1);
        g_col[pos] = src[i];
    }
}

// ---------------------------------------------------------------------------
// K4: Y[row] = x_sparse[row] @ W_neigh, fused duplicate-index dedup
//     (last-k-wins to match JAX scatter-set). One warp per node;
//     lane owns 4 output columns. W rows come from L1 (64KB, resident).
// ---------------------------------------------------------------------------
__global__ __launch_bounds__(256)
void y_kernel(const int* __restrict__ tindices,
              const float* __restrict__ tvalues,
              const float* __restrict__ Wneigh, int n) {
    int wrp  = blockIdx.x * 8 + (threadIdx.x >> 5);
    int lane = threadIdx.x & 31;
    if (wrp >= n) return;
    int   idx = tindices[wrp * KTOP + lane];
    float v   = tvalues[wrp * KTOP + lane];
    unsigned m = __match_any_sync(FULLM, idx);
    if (lane != 31 - __clz(m)) v = 0.0f;   // highest-k lane wins among duplicates

    float4 acc = make_float4(0.f, 0.f, 0.f, 0.f);
#pragma unroll
    for (int k = 0; k < KTOP; k++) {
        int   ik = __shfl_sync(FULLM, idx, k);
        float vk = __shfl_sync(FULLM, v, k);
        if (vk != 0.0f) {   // warp-uniform branch
            float4 w = __ldg((const float4*)(Wneigh + ik * NFEAT) + lane);
            acc.x = fmaf(vk, w.x, acc.x);
            acc.y = fmaf(vk, w.y, acc.y);
            acc.z = fmaf(vk, w.z, acc.z);
            acc.w = fmaf(vk, w.w, acc.w);
        }
    }
    *((float4*)(g_Y + (size_t)wrp * NFEAT) + lane) = acc;
}

// ---------------------------------------------------------------------------
// K5: CSR gather: hagg[d] = (1/max(deg,1)) * sum_{s in N(d)} Y[s]
//     One warp per dst node; lane owns 4 columns. Atomic-free.
// ---------------------------------------------------------------------------
__global__ __launch_bounds__(256)
void gather_kernel(int n) {
    int d    = blockIdx.x * 8 + (threadIdx.x >> 5);
    int lane = threadIdx.x & 31;
    if (d >= n) return;
    int start = g_rowstart[d];
    int cnt   = g_cnt[d];

    float4 acc = make_float4(0.f, 0.f, 0.f, 0.f);
    for (int i = 0; i < cnt; i += 32) {
        int s = (i + lane < cnt) ? g_col[start + i + lane] : 0;
        int m = min(32, cnt - i);
        for (int j = 0; j < m; j++) {
            int sj = __shfl_sync(FULLM, s, j);
            float4 y = *((const float4*)(g_Y + (size_t)sj * NFEAT) + lane);
            acc.x += y.x; acc.y += y.y; acc.z += y.z; acc.w += y.w;
        }
    }
    float w = 1.0f / fmaxf((float)cnt, 1.0f);
    float4 o = make_float4(acc.x * w, acc.y * w, acc.z * w, acc.w * w);
    *((float4*)(g_hagg + (size_t)d * NFEAT) + lane) = o;
}

// ---------------------------------------------------------------------------
// K6: out = feat @ W_self + b_self + hagg
//     128x128 block tile, 8x8 register tile, conflict-free B reads
//     (per-thread cols = {tx*4..tx*4+3} U {64+tx*4..64+tx*4+3}).
// ---------------------------------------------------------------------------
__global__ __launch_bounds__(256, 2)
void gemm_kernel(const float* __restrict__ feat,
                 const float* __restrict__ Wself,
                 const float* __restrict__ bself,
                 float* __restrict__ out, int n) {
    __shared__ float a_sh[16][132];   // [k][row], padded
    __shared__ float w_sh[16][128];   // [k][col]

    const int row0 = blockIdx.x * 128;
    const int tid  = threadIdx.x;
    const int tx   = tid & 15;        // col group
    const int ty   = tid >> 4;        // row group (8 rows)

    float acc[8][8];
#pragma unroll
    for (int i = 0; i < 8; i++)
#pragma unroll
        for (int j = 0; j < 8; j++) acc[i][j] = 0.0f;

#pragma unroll 1
    for (int k0 = 0; k0 < NFEAT; k0 += 16) {
        // stage A tile, transposed [k][row]
        {
            int r  = tid & 127;
            int kb = (tid >> 7) << 3;   // 0 or 8
            float4 v0 = make_float4(0.f, 0.f, 0.f, 0.f);
            float4 v1 = v0;
            if (row0 + r < n) {
                const float* ap = feat + (size_t)(row0 + r) * NFEAT + k0 + kb;
                v0 = *(const float4*)ap;
                v1 = *(const float4*)(ap + 4);
            }
            a_sh[kb + 0][r] = v0.x; a_sh[kb + 1][r] = v0.y;
            a_sh[kb + 2][r] = v0.z; a_sh[kb + 3][r] = v0.w;
            a_sh[kb + 4][r] = v1.x; a_sh[kb + 5][r] = v1.y;
            a_sh[kb + 6][r] = v1.z; a_sh[kb + 7][r] = v1.w;
        }
        // stage W tile
        {
            int kk = tid >> 5;
            int c4 = (tid & 31) << 2;
            *(float4*)&w_sh[kk][c4]     = *(const float4*)&Wself[(k0 + kk) * NFEAT + c4];
            *(float4*)&w_sh[kk + 8][c4] = *(const float4*)&Wself[(k0 + kk + 8) * NFEAT + c4];
        }
        __syncthreads();

#pragma unroll
        for (int kq = 0; kq < 16; kq++) {
            float a[8], b[8];
            *(float4*)&a[0] = *(const float4*)&a_sh[kq][ty * 8];
            *(float4*)&a[4] = *(const float4*)&a_sh[kq][ty * 8 + 4];
            *(float4*)&b[0] = *(const float4*)&w_sh[kq][tx * 4];        // phase-local 128B
            *(float4*)&b[4] = *(const float4*)&w_sh[kq][64 + tx * 4];   // phase-local 128B
#pragma unroll
            for (int i = 0; i < 8; i++)
#pragma unroll
                for (int j = 0; j < 8; j++)
                    acc[i][j] = fmaf(a[i], b[j], acc[i][j]);
        }
        __syncthreads();
    }

    // epilogue: + bias + hagg, store
    const int c0 = tx * 4;
    const int c1 = 64 + tx * 4;
    float4 b0 = __ldg((const float4*)(bself + c0));
    float4 b1 = __ldg((const float4*)(bself + c1));
#pragma unroll
    for (int i = 0; i < 8; i++) {
        int rr = row0 + ty * 8 + i;
        if (rr < n) {
            float4 h0 = *(const float4*)(g_hagg + (size_t)rr * NFEAT + c0);
            float4 h1 = *(const float4*)(g_hagg + (size_t)rr * NFEAT + c1);
            float4 o0, o1;
            o0.x = acc[i][0] + b0.x + h0.x;
            o0.y = acc[i][1] + b0.y + h0.y;
            o0.z = acc[i][2] + b0.z + h0.z;
            o0.w = acc[i][3] + b0.w + h0.w;
            o1.x = acc[i][4] + b1.x + h1.x;
            o1.y = acc[i][5] + b1.y + h1.y;
            o1.z = acc[i][6] + b1.z + h1.z;
            o1.w = acc[i][7] + b1.w + h1.w;
            *(float4*)(out + (size_t)rr * NFEAT + c0) = o0;
            *(float4*)(out + (size_t)rr * NFEAT + c1) = o1;
        }
    }
}

// ---------------------------------------------------------------------------
// Launch. Input order: 0 feat | 1 topk_values | 2 topk_indices | 3 src |
//                      4 dst | 5 W_self | 6 b_self | 7 W_neigh
// ---------------------------------------------------------------------------
extern "C" void kernel_launch(void* const* d_in, const int* in_sizes, int n_in,
                              void* d_out, int out_size) {
    const float* feat     = (const float*)d_in[0];
    const float* tvalues  = (const float*)d_in[1];
    const int*   tindices = (const int*)d_in[2];
    const int*   src      = (const int*)d_in[3];
    const int*   dst      = (const int*)d_in[4];
    const float* Wself    = (const float*)d_in[5];
    const float* bself    = (const float*)d_in[6];
    const float* Wneigh   = (const float*)d_in[7];
    float*       out      = (float*)d_out;

    const int n = in_sizes[0] / NFEAT;   // 50000
    const int e = in_sizes[3];           // 800000

    void* cntp;
    cudaGetSymbolAddress(&cntp, g_cnt);
    cudaMemsetAsync(cntp, 0, (size_t)n * sizeof(int));

    const int nblk = (n + 255) / 256;    // 196

    count_kernel<<<(e + 255) / 256, 256>>>(dst, e);
    blocksum_kernel<<<nblk, 256>>>();
    scanpartials_kernel<<<1, 256>>>(nblk);
    localscan_kernel<<<nblk, 256>>>();
    fill_kernel<<<(e + 255) / 256, 256>>>(src, dst, e);

    y_kernel<<<(n + 7) / 8, 256>>>(tindices, tvalues, Wneigh, n);
    gather_kernel<<<(n + 7) / 8, 256>>>(n);
    gemm_kernel<<<(n + 127) / 128, 256>>>(feat, Wself, bself, out, n);
}